// round 1
// baseline (speedup 1.0000x reference)
#include <cuda_runtime.h>
#include <cstdint>

// Problem constants (fixed by the reference: B=8, S=4096, D=1024)
#define BB 8
#define SS 4096
#define DD 1024

// Scratch for per-batch inclusive cumsum of boundary_mask. 8*4096*4B = 128 KB.
__device__ int g_cum[BB * SS];

// ---------------------------------------------------------------------------
// Kernel A: per-batch inclusive prefix sum of the boundary mask.
// One block per batch, 1024 threads, 4 elements per thread.
// ---------------------------------------------------------------------------
__global__ __launch_bounds__(1024) void cumsum_kernel(const int* __restrict__ mask) {
    __shared__ int warp_sums[32];

    const int b = blockIdx.x;
    const int t = threadIdx.x;
    const int lane = t & 31;
    const int warp = t >> 5;

    const int* m = mask + b * SS;
    int* out = g_cum + b * SS;

    // Load 4 contiguous mask values per thread, local inclusive scan.
    const int base_idx = t * 4;
    int v0 = (m[base_idx + 0] != 0);
    int v1 = (m[base_idx + 1] != 0);
    int v2 = (m[base_idx + 2] != 0);
    int v3 = (m[base_idx + 3] != 0);
    int s0 = v0;
    int s1 = s0 + v1;
    int s2 = s1 + v2;
    int s3 = s2 + v3;
    const int tot = s3;

    // Warp-level inclusive scan of per-thread totals.
    int x = tot;
    #pragma unroll
    for (int o = 1; o < 32; o <<= 1) {
        int y = __shfl_up_sync(0xFFFFFFFFu, x, o);
        if (lane >= o) x += y;
    }
    if (lane == 31) warp_sums[warp] = x;
    __syncthreads();

    // Warp 0 scans the 32 warp totals.
    if (warp == 0) {
        int w = warp_sums[lane];
        #pragma unroll
        for (int o = 1; o < 32; o <<= 1) {
            int y = __shfl_up_sync(0xFFFFFFFFu, w, o);
            if (lane >= o) w += y;
        }
        warp_sums[lane] = w;
    }
    __syncthreads();

    // Exclusive prefix for this thread.
    const int warp_base = (warp > 0) ? warp_sums[warp - 1] : 0;
    const int excl = warp_base + x - tot;

    out[base_idx + 0] = excl + s0;
    out[base_idx + 1] = excl + s1;
    out[base_idx + 2] = excl + s2;
    out[base_idx + 3] = excl + s3;
}

// ---------------------------------------------------------------------------
// Kernel B: y[b,j,:] = cum>0 ? compressed[b, cum-1, :] : 0
// One float4 per thread. 256 float4 per (b,j) row (D=1024).
// Writes fully coalesced; gather reads coalesced per row, repeats hit L2.
// ---------------------------------------------------------------------------
__global__ __launch_bounds__(256) void gather_kernel(const float4* __restrict__ comp,
                                                     float4* __restrict__ out) {
    const int gid = blockIdx.x * 256 + threadIdx.x;   // global float4 index
    const int row = gid >> 8;                         // (b*S + j), 256 float4/row
    const int c   = gid & 255;                        // float4 column within D

    const int cum = g_cum[row];
    const int b   = row >> 12;                        // S = 4096 rows per batch

    float4 val = make_float4(0.f, 0.f, 0.f, 0.f);
    if (cum > 0) {
        const size_t src_row = (size_t)(b << 12) + (size_t)(cum - 1);
        val = __ldg(comp + src_row * 256 + c);
    }
    out[gid] = val;
}

// ---------------------------------------------------------------------------
// Inputs (metadata order):
//   d_in[0]: compressed_states  float32 [8, 4096, 1024]
//   d_in[1]: boundary_prob      float32 [8, 4096, 2]   (unused — math collapses)
//   d_in[2]: boundary_mask      bool -> int32 [8, 4096]
// Output: float32 [8, 4096, 1024]
// ---------------------------------------------------------------------------
extern "C" void kernel_launch(void* const* d_in, const int* in_sizes, int n_in,
                              void* d_out, int out_size) {
    const float* comp = (const float*)d_in[0];
    const int*   mask = (const int*)d_in[2];
    float* out = (float*)d_out;

    cumsum_kernel<<<BB, 1024>>>(mask);

    const int total_f4 = BB * SS * (DD / 4);          // 8,388,608
    gather_kernel<<<total_f4 / 256, 256>>>((const float4*)comp, (float4*)out);
}

// round 2
// speedup vs baseline: 1.2706x; 1.2706x over previous
#include <cuda_runtime.h>
#include <cstdint>

// Problem constants (fixed by the reference: B=8, S=4096, D=1024)
#define BB 8
#define SS 4096
#define DD 1024

// Scratch for per-batch inclusive cumsum of boundary_mask. 8*4096*4B = 128 KB.
__device__ int g_cum[BB * SS];

// ---------------------------------------------------------------------------
// Kernel A: per-batch inclusive prefix sum of the boundary mask.
// One block per batch, 1024 threads, 4 elements per thread (int4 I/O).
// ---------------------------------------------------------------------------
__global__ __launch_bounds__(1024) void cumsum_kernel(const int4* __restrict__ mask) {
    __shared__ int warp_sums[32];

    const int b = blockIdx.x;
    const int t = threadIdx.x;
    const int lane = t & 31;
    const int warp = t >> 5;

    const int4* m = mask + b * (SS / 4);
    int4* out = (int4*)(g_cum + b * SS);

    int4 v = m[t];
    int s0 = (v.x != 0);
    int s1 = s0 + (v.y != 0);
    int s2 = s1 + (v.z != 0);
    int s3 = s2 + (v.w != 0);
    const int tot = s3;

    // Warp-level inclusive scan of per-thread totals.
    int x = tot;
    #pragma unroll
    for (int o = 1; o < 32; o <<= 1) {
        int y = __shfl_up_sync(0xFFFFFFFFu, x, o);
        if (lane >= o) x += y;
    }
    if (lane == 31) warp_sums[warp] = x;
    __syncthreads();

    if (warp == 0) {
        int w = warp_sums[lane];
        #pragma unroll
        for (int o = 1; o < 32; o <<= 1) {
            int y = __shfl_up_sync(0xFFFFFFFFu, w, o);
            if (lane >= o) w += y;
        }
        warp_sums[lane] = w;
    }
    __syncthreads();

    const int warp_base = (warp > 0) ? warp_sums[warp - 1] : 0;
    const int excl = warp_base + x - tot;

    out[t] = make_int4(excl + s0, excl + s1, excl + s2, excl + s3);
}

// ---------------------------------------------------------------------------
// Kernel B: y[b,j,:] = cum>0 ? compressed[b, cum-1, :] : 0
//
// Block of 256 threads handles 4 output rows (4 KB each).
//   sub = t>>6 selects the row, c = t&63 the base float4 column.
//   Each thread issues 4 independent float4 loads (cols c, c+64, c+128, c+192)
//   -> MLP=4 per thread, coalesced 128B per warp per load.
// Streaming stores (__stcs) keep the output from evicting `compressed` rows
// out of L2, so duplicate-row gathers stay L2-resident.
// ---------------------------------------------------------------------------
__global__ __launch_bounds__(256) void gather_kernel(const float4* __restrict__ comp,
                                                     float4* __restrict__ out) {
    const int t    = threadIdx.x;
    const int sub  = t >> 6;                          // 0..3: row within block
    const int c    = t & 63;                          // base float4 column
    const int row  = blockIdx.x * 4 + sub;            // global (b*S + j)
    const int b    = row >> 12;                       // S = 4096 rows per batch

    const int cum = g_cum[row];

    float4* o = out + (size_t)row * 256 + c;

    if (cum > 0) {
        const float4* s = comp + ((size_t)(b << 12) + (size_t)(cum - 1)) * 256 + c;
        float4 v0 = __ldg(s);
        float4 v1 = __ldg(s + 64);
        float4 v2 = __ldg(s + 128);
        float4 v3 = __ldg(s + 192);
        __stcs(o,       v0);
        __stcs(o + 64,  v1);
        __stcs(o + 128, v2);
        __stcs(o + 192, v3);
    } else {
        const float4 z = make_float4(0.f, 0.f, 0.f, 0.f);
        __stcs(o,       z);
        __stcs(o + 64,  z);
        __stcs(o + 128, z);
        __stcs(o + 192, z);
    }
}

// ---------------------------------------------------------------------------
// Inputs (metadata order):
//   d_in[0]: compressed_states  float32 [8, 4096, 1024]
//   d_in[1]: boundary_prob      float32 [8, 4096, 2]   (unused — math collapses)
//   d_in[2]: boundary_mask      bool -> int32 [8, 4096]
// Output: float32 [8, 4096, 1024]
// ---------------------------------------------------------------------------
extern "C" void kernel_launch(void* const* d_in, const int* in_sizes, int n_in,
                              void* d_out, int out_size) {
    const float* comp = (const float*)d_in[0];
    const int*   mask = (const int*)d_in[2];
    float* out = (float*)d_out;

    cumsum_kernel<<<BB, 1024>>>((const int4*)mask);

    gather_kernel<<<(BB * SS) / 4, 256>>>((const float4*)comp, (float4*)out);
}